// round 9
// baseline (speedup 1.0000x reference)
#include <cuda_runtime.h>
#include <cuda_bf16.h>
#include <stdint.h>
#include <math.h>

#define C_DIM  1024
#define CI_DIM 256
#define B_DIM  16
#define N_DIM  2048
#define BN_EPS 1e-5f

typedef __nv_bfloat16 bf16;

// ---------------------------------------------------------------------------
// Static device scratch (hi/lo split-precision planes)
// ---------------------------------------------------------------------------
__device__ bf16 g_xT_hi[(size_t)B_DIM * N_DIM * C_DIM];
__device__ bf16 g_xT_lo[(size_t)B_DIM * N_DIM * C_DIM];
__device__ bf16 g_tw_hi[CI_DIM * C_DIM], g_tw_lo[CI_DIM * C_DIM];
__device__ bf16 g_pw_hi[CI_DIM * C_DIM], g_pw_lo[CI_DIM * C_DIM];
__device__ bf16 g_gw_hi[CI_DIM * C_DIM], g_gw_lo[CI_DIM * C_DIM];
__device__ bf16 g_ww_hi[C_DIM * CI_DIM], g_ww_lo[C_DIM * CI_DIM];
__device__ bf16 g_th_hi[(size_t)B_DIM * N_DIM * CI_DIM], g_th_lo[(size_t)B_DIM * N_DIM * CI_DIM];
__device__ bf16 g_ph_hi[(size_t)B_DIM * N_DIM * CI_DIM], g_ph_lo[(size_t)B_DIM * N_DIM * CI_DIM];
__device__ bf16 g_gv_hi[(size_t)B_DIM * CI_DIM * N_DIM], g_gv_lo[(size_t)B_DIM * CI_DIM * N_DIM];
__device__ float g_S[(size_t)B_DIM * N_DIM * N_DIM];
__device__ bf16 g_P_hi[(size_t)B_DIM * N_DIM * N_DIM], g_P_lo[(size_t)B_DIM * N_DIM * N_DIM];
__device__ bf16 g_y_hi[(size_t)B_DIM * N_DIM * CI_DIM], g_y_lo[(size_t)B_DIM * N_DIM * CI_DIM];

// ---------------------------------------------------------------------------
// PTX helpers (sm_80+ base features only — target is plain sm_103)
// ---------------------------------------------------------------------------
__device__ __forceinline__ uint32_t smem_u32(const void* p) {
    uint32_t a;
    asm("{ .reg .u64 t; cvta.to.shared.u64 t, %1; cvt.u32.u64 %0, t; }" : "=r"(a) : "l"(p));
    return a;
}
__device__ __forceinline__ void cpasync16(uint32_t s, const void* g) {
    asm volatile("cp.async.cg.shared.global [%0], [%1], 16;\n" :: "r"(s), "l"(g));
}
#define CP_COMMIT() asm volatile("cp.async.commit_group;" ::: "memory")
#define CP_WAIT(n)  asm volatile("cp.async.wait_group %0;" :: "n"(n) : "memory")

#define LDSM4(r0, r1, r2, r3, addr) \
    asm volatile("ldmatrix.sync.aligned.m8n8.x4.shared.b16 {%0,%1,%2,%3}, [%4];" \
        : "=r"(r0), "=r"(r1), "=r"(r2), "=r"(r3) : "r"(addr))

#define MMA_BF16(d, a, b) \
    asm volatile("mma.sync.aligned.m16n8k16.row.col.f32.bf16.bf16.f32 " \
        "{%0,%1,%2,%3}, {%4,%5,%6,%7}, {%8,%9}, {%0,%1,%2,%3};" \
        : "+f"((d)[0]), "+f"((d)[1]), "+f"((d)[2]), "+f"((d)[3]) \
        : "r"((a)[0]), "r"((a)[1]), "r"((a)[2]), "r"((a)[3]), "r"((b)[0]), "r"((b)[1]))

// ---------------------------------------------------------------------------
// Generic split-bf16 HMMA GEMM:  D[i,j] = sum_k A[i,k]*B[j,k]
//   CTA tile 128x128, K-chunk 64, 3-stage cp.async pipeline.
//   8 warps, warp tile 64x32 (2x4 warp grid).
//   Stage layout (128B rows, XOR-8 swizzle on 16B chunks):
//     Ah @0, Al @16384, Bh @32768, Bl @49152 ; stage stride 65536.
//   mode 0: bf16 hi/lo out (+optional bias_i[i], bias_j[j]), out[j*ldo+i]
//   mode 1: fp32 out[j*ldo+i]
//   mode 2: fp32 out = D*inv[j] + shift[j] + xres  (BN + residual)
// ---------------------------------------------------------------------------
#define STAGE_BYTES 65536
#define NSTAGE 3
#define EPI_PITCH   132
#define SMEM_BYTES  (NSTAGE * STAGE_BYTES)   // 196608; epi staging (67.5KB) reuses it

__device__ __forceinline__ uint32_t swz128(int row, int ch) {
    return (uint32_t)(row * 128 + ((ch ^ (row & 7)) << 4));
}
__device__ __forceinline__ uint32_t ldsm_addr(uint32_t pbase, int rbase, int c0, int lane) {
    const int r = rbase + (lane & 15);
    const int c = c0 + (lane >> 4);
    return pbase + swz128(r, c);
}

__device__ __forceinline__ void fill_stage(uint32_t sbase,
    const bf16* __restrict__ Ah, const bf16* __restrict__ Al,
    const bf16* __restrict__ Bh, const bf16* __restrict__ Bl,
    int i0, int j0, int koff, int K)
{
    const int t = threadIdx.x;
#pragma unroll
    for (int rep = 0; rep < 4; rep++) {
        const int e = t + rep * 256;        // 0..1023
        const int row = e >> 3;             // 0..127
        const int ch  = e & 7;              // 16B chunk within 128B row
        const uint32_t so = swz128(row, ch);
        const size_t ka = (size_t)(i0 + row) * K + koff + ch * 8;
        const size_t kb = (size_t)(j0 + row) * K + koff + ch * 8;
        cpasync16(sbase + so,         Ah + ka);
        cpasync16(sbase + 16384 + so, Al + ka);
        cpasync16(sbase + 32768 + so, Bh + kb);
        cpasync16(sbase + 49152 + so, Bl + kb);
    }
}

__global__ __launch_bounds__(256, 1)
void gemm_kernel(const bf16* __restrict__ Ahi, const bf16* __restrict__ Alo,
                 const bf16* __restrict__ Bhi, const bf16* __restrict__ Blo,
                 long long sA, long long sB, int K,
                 bf16* __restrict__ Ohi, bf16* __restrict__ Olo, float* __restrict__ O32,
                 long long sO, int ldo,
                 const float* __restrict__ bias_i, const float* __restrict__ bias_j,
                 int mode,
                 const float* __restrict__ gamma, const float* __restrict__ beta,
                 const float* __restrict__ mean, const float* __restrict__ var,
                 const float* __restrict__ wbias, const float* __restrict__ xres)
{
    extern __shared__ char dsm[];
    const int t = threadIdx.x, lane = t & 31, wid = t >> 5;
    const int wm = wid >> 2, wn = wid & 3;       // 2 x 4 warp grid
    const int b = blockIdx.z;
    const int i0 = blockIdx.y * 128, j0 = blockIdx.x * 128;

    const bf16* Ah = Ahi + (size_t)b * sA;
    const bf16* Al = Alo + (size_t)b * sA;
    const bf16* Bh = Bhi + (size_t)b * sB;
    const bf16* Bl = Blo + (size_t)b * sB;

    const uint32_t sb = smem_u32(dsm);

    float acc[4][4][4] = {};

    const int nk = K >> 6;   // 64-wide K chunks

    // prologue: fill stages 0,1
    fill_stage(sb,               Ah, Al, Bh, Bl, i0, j0, 0,  K);
    CP_COMMIT();
    if (nk > 1) fill_stage(sb + STAGE_BYTES, Ah, Al, Bh, Bl, i0, j0, 64, K);
    CP_COMMIT();

    int stg = 0;
    for (int k = 0; k < nk; k++) {
        // fill chunk k+2 into stage (k+2)%3; always commit (possibly empty group)
        if (k + 2 < nk) {
            int ns = stg + 2; if (ns >= NSTAGE) ns -= NSTAGE;
            fill_stage(sb + ns * STAGE_BYTES, Ah, Al, Bh, Bl, i0, j0, (k + 2) << 6, K);
        }
        CP_COMMIT();
        CP_WAIT(2);          // pending = groups k+1, k+2  ->  group k complete
        __syncthreads();     // all warps done with chunk k-1 regs/ldsm before its stage refill

        const uint32_t base = sb + stg * STAGE_BYTES;
#pragma unroll
        for (int ks = 0; ks < 4; ks++) {
            const int c0 = ks * 2;
            uint32_t ah[4][4], al[4][4], bh[4][2], bl[4][2];
#pragma unroll
            for (int mi = 0; mi < 4; mi++) {
                const int rb = wm * 64 + mi * 16;
                LDSM4(ah[mi][0], ah[mi][1], ah[mi][2], ah[mi][3], ldsm_addr(base,         rb, c0, lane));
                LDSM4(al[mi][0], al[mi][1], al[mi][2], al[mi][3], ldsm_addr(base + 16384, rb, c0, lane));
            }
#pragma unroll
            for (int nip = 0; nip < 2; nip++) {
                const int rb = wn * 32 + nip * 16;
                uint32_t r0, r1, r2, r3;
                LDSM4(r0, r1, r2, r3, ldsm_addr(base + 32768, rb, c0, lane));
                bh[nip * 2][0] = r0; bh[nip * 2 + 1][0] = r1;
                bh[nip * 2][1] = r2; bh[nip * 2 + 1][1] = r3;
                LDSM4(r0, r1, r2, r3, ldsm_addr(base + 49152, rb, c0, lane));
                bl[nip * 2][0] = r0; bl[nip * 2 + 1][0] = r1;
                bl[nip * 2][1] = r2; bl[nip * 2 + 1][1] = r3;
            }
#pragma unroll
            for (int mi = 0; mi < 4; mi++)
#pragma unroll
                for (int ni = 0; ni < 4; ni++) {
                    MMA_BF16(acc[mi][ni], ah[mi], bh[ni]);
                    MMA_BF16(acc[mi][ni], ah[mi], bl[ni]);
                    MMA_BF16(acc[mi][ni], al[mi], bh[ni]);
                }
        }
        if (++stg >= NSTAGE) stg = 0;
    }

    // ---- epilogue: stage fp32 tile through smem (pitch 132), coalesced out ----
    __syncthreads();
    float* sf = (float*)dsm;
    {
        const int r0 = lane >> 2;
        const int cpair = (lane & 3) << 1;
#pragma unroll
        for (int mi = 0; mi < 4; mi++)
#pragma unroll
            for (int ni = 0; ni < 4; ni++) {
                const int il = wm * 64 + mi * 16 + r0;
                const int jl = wn * 32 + ni * 8 + cpair;
                sf[jl * EPI_PITCH + il]           = acc[mi][ni][0];
                sf[(jl + 1) * EPI_PITCH + il]     = acc[mi][ni][1];
                sf[jl * EPI_PITCH + il + 8]       = acc[mi][ni][2];
                sf[(jl + 1) * EPI_PITCH + il + 8] = acc[mi][ni][3];
            }
    }
    __syncthreads();

#pragma unroll 4
    for (int rep = 0; rep < 64; rep++) {
        const int idx = rep * 256 + t;
        const int jl = idx >> 7, il = idx & 127;
        float v = sf[jl * EPI_PITCH + il];
        const int i = i0 + il;
        const int jg = j0 + jl;
        if (mode == 0) {
            if (bias_i) v += bias_i[i];
            if (bias_j) v += bias_j[jg];
            const bf16 h = __float2bfloat16(v);
            const float lo = v - __bfloat162float(h);
            const size_t a = (size_t)b * sO + (size_t)jg * ldo + i;
            Ohi[a] = h;
            Olo[a] = __float2bfloat16(lo);
        } else if (mode == 1) {
            O32[(size_t)b * sO + (size_t)jg * ldo + i] = v;
        } else {
            const float iv = gamma[jg] * rsqrtf(var[jg] + BN_EPS);
            const float sh = beta[jg] + (wbias[jg] - mean[jg]) * iv;
            const size_t a = (size_t)b * sO + (size_t)jg * ldo + i;
            O32[a] = v * iv + sh + xres[a];
        }
    }
}

// ---------------------------------------------------------------------------
// All 4 weight tensors split in one launch
// ---------------------------------------------------------------------------
#define W3_ELEMS (CI_DIM * C_DIM)
__global__ void conv_split4(const float* __restrict__ tw, const float* __restrict__ pw,
                            const float* __restrict__ gw, const float* __restrict__ ww)
{
    const int idx = blockIdx.x * 256 + threadIdx.x;   // 0 .. 4*W3_ELEMS-1
    const int sel = idx / W3_ELEMS;
    const int off = idx - sel * W3_ELEMS;
    const float* in = (sel == 0) ? tw : (sel == 1) ? pw : (sel == 2) ? gw : ww;
    bf16* hi = (sel == 0) ? g_tw_hi : (sel == 1) ? g_pw_hi : (sel == 2) ? g_gw_hi : g_ww_hi;
    bf16* lo = (sel == 0) ? g_tw_lo : (sel == 1) ? g_pw_lo : (sel == 2) ? g_gw_lo : g_ww_lo;
    const float v = in[off];
    const bf16 h = __float2bfloat16(v);
    hi[off] = h;
    lo[off] = __float2bfloat16(v - __bfloat162float(h));
}

// ---------------------------------------------------------------------------
// x [B,C,N] fp32 -> xT [B,N,C] bf16 hi/lo  (32x32 smem transpose)
// ---------------------------------------------------------------------------
__global__ __launch_bounds__(256)
void transpose_split(const float* __restrict__ x)
{
    __shared__ float tb[32][33];
    const int b = blockIdx.z;
    const int c0 = blockIdx.y * 32;
    const int n0 = blockIdx.x * 32;
    const int tx = threadIdx.x & 31, ty = threadIdx.x >> 5;
#pragma unroll
    for (int it = 0; it < 4; it++)
        tb[ty + it * 8][tx] = x[((size_t)b * C_DIM + c0 + ty + it * 8) * N_DIM + n0 + tx];
    __syncthreads();
#pragma unroll
    for (int it = 0; it < 4; it++) {
        const float v = tb[tx][ty + it * 8];
        const size_t a = ((size_t)b * N_DIM + n0 + ty + it * 8) * C_DIM + c0 + tx;
        const bf16 h = __float2bfloat16(v);
        g_xT_hi[a] = h;
        g_xT_lo[a] = __float2bfloat16(v - __bfloat162float(h));
    }
}

// ---------------------------------------------------------------------------
// Row softmax: S fp32 [row][2048] -> P hi/lo bf16
// ---------------------------------------------------------------------------
__global__ __launch_bounds__(256)
void softmax_split()
{
    const size_t row = (size_t)blockIdx.x * N_DIM;
    const float* __restrict__ s = g_S + row;
    __shared__ float buf[N_DIM];
    __shared__ float red[8];
    const int tid = threadIdx.x, lane = tid & 31, warp = tid >> 5;

    float lmax = -INFINITY;
#pragma unroll
    for (int it = 0; it < N_DIM / 256; it++) {
        float v = s[tid + it * 256];
        buf[tid + it * 256] = v;
        lmax = fmaxf(lmax, v);
    }
#pragma unroll
    for (int o = 16; o; o >>= 1) lmax = fmaxf(lmax, __shfl_xor_sync(0xffffffffu, lmax, o));
    if (lane == 0) red[warp] = lmax;
    __syncthreads();
    float m = red[0];
#pragma unroll
    for (int w = 1; w < 8; w++) m = fmaxf(m, red[w]);
    __syncthreads();

    float lsum = 0.f;
#pragma unroll
    for (int it = 0; it < N_DIM / 256; it++) {
        float e = __expf(buf[tid + it * 256] - m);
        buf[tid + it * 256] = e;
        lsum += e;
    }
#pragma unroll
    for (int o = 16; o; o >>= 1) lsum += __shfl_xor_sync(0xffffffffu, lsum, o);
    if (lane == 0) red[warp] = lsum;
    __syncthreads();
    float tot = red[0];
#pragma unroll
    for (int w = 1; w < 8; w++) tot += red[w];
    const float inv = 1.f / tot;

#pragma unroll
    for (int it = 0; it < N_DIM / 256; it++) {
        const int idx = tid + it * 256;
        const float p = buf[idx] * inv;
        const bf16 h = __float2bfloat16(p);
        g_P_hi[row + idx] = h;
        g_P_lo[row + idx] = __float2bfloat16(p - __bfloat162float(h));
    }
}

// ---------------------------------------------------------------------------
// Launch
// ---------------------------------------------------------------------------
extern "C" void kernel_launch(void* const* d_in, const int* in_sizes, int n_in,
                              void* d_out, int out_size)
{
    const float* x        = (const float*)d_in[0];
    const float* theta_w  = (const float*)d_in[1];
    const float* theta_b  = (const float*)d_in[2];
    const float* phi_w    = (const float*)d_in[3];
    const float* phi_b    = (const float*)d_in[4];
    const float* g_w      = (const float*)d_in[5];
    const float* g_b      = (const float*)d_in[6];
    const float* w_w      = (const float*)d_in[7];
    const float* w_b      = (const float*)d_in[8];
    const float* bn_gamma = (const float*)d_in[9];
    const float* bn_beta  = (const float*)d_in[10];
    const float* bn_mean  = (const float*)d_in[11];
    const float* bn_var   = (const float*)d_in[12];
    float* out = (float*)d_out;

    cudaFuncSetAttribute(gemm_kernel, cudaFuncAttributeMaxDynamicSharedMemorySize, SMEM_BYTES);

    bf16 *xt_hi, *xt_lo, *tw_hi, *tw_lo, *pw_hi, *pw_lo, *gw_hi, *gw_lo, *ww_hi, *ww_lo;
    bf16 *th_hi, *th_lo, *ph_hi, *ph_lo, *gv_hi, *gv_lo, *P_hi, *P_lo, *y_hi, *y_lo;
    float* Sp;
    cudaGetSymbolAddress((void**)&xt_hi, g_xT_hi); cudaGetSymbolAddress((void**)&xt_lo, g_xT_lo);
    cudaGetSymbolAddress((void**)&tw_hi, g_tw_hi); cudaGetSymbolAddress((void**)&tw_lo, g_tw_lo);
    cudaGetSymbolAddress((void**)&pw_hi, g_pw_hi); cudaGetSymbolAddress((void**)&pw_lo, g_pw_lo);
    cudaGetSymbolAddress((void**)&gw_hi, g_gw_hi); cudaGetSymbolAddress((void**)&gw_lo, g_gw_lo);
    cudaGetSymbolAddress((void**)&ww_hi, g_ww_hi); cudaGetSymbolAddress((void**)&ww_lo, g_ww_lo);
    cudaGetSymbolAddress((void**)&th_hi, g_th_hi); cudaGetSymbolAddress((void**)&th_lo, g_th_lo);
    cudaGetSymbolAddress((void**)&ph_hi, g_ph_hi); cudaGetSymbolAddress((void**)&ph_lo, g_ph_lo);
    cudaGetSymbolAddress((void**)&gv_hi, g_gv_hi); cudaGetSymbolAddress((void**)&gv_lo, g_gv_lo);
    cudaGetSymbolAddress((void**)&P_hi,  g_P_hi);  cudaGetSymbolAddress((void**)&P_lo,  g_P_lo);
    cudaGetSymbolAddress((void**)&y_hi,  g_y_hi);  cudaGetSymbolAddress((void**)&y_lo,  g_y_lo);
    cudaGetSymbolAddress((void**)&Sp,    g_S);

    // 0) weight splits (one launch) + x transpose/split
    conv_split4<<<4 * W3_ELEMS / 256, 256>>>(theta_w, phi_w, g_w, w_w);
    transpose_split<<<dim3(N_DIM / 32, C_DIM / 32, B_DIM), 256>>>(x);

    const long long sNC  = (long long)N_DIM * C_DIM;
    const long long sNCI = (long long)N_DIM * CI_DIM;
    const long long sCIN = (long long)CI_DIM * N_DIM;
    const long long sNN  = (long long)N_DIM * N_DIM;
    const long long sCN  = (long long)C_DIM * N_DIM;

    // 1) theta: D[o,n] = sum_c tw[o,c] * xT[n,c]  -> th [B,N,CI]
    gemm_kernel<<<dim3(N_DIM / 128, CI_DIM / 128, B_DIM), 256, SMEM_BYTES>>>(
        tw_hi, tw_lo, xt_hi, xt_lo, 0, sNC, C_DIM,
        th_hi, th_lo, nullptr, sNCI, CI_DIM, theta_b, nullptr, 0,
        nullptr, nullptr, nullptr, nullptr, nullptr, nullptr);
    // 2) phi
    gemm_kernel<<<dim3(N_DIM / 128, CI_DIM / 128, B_DIM), 256, SMEM_BYTES>>>(
        pw_hi, pw_lo, xt_hi, xt_lo, 0, sNC, C_DIM,
        ph_hi, ph_lo, nullptr, sNCI, CI_DIM, phi_b, nullptr, 0,
        nullptr, nullptr, nullptr, nullptr, nullptr, nullptr);
    // 3) g: D[n,ci] = sum_c xT[n,c] * gw[ci,c]  -> gv [B,CI,N]
    gemm_kernel<<<dim3(CI_DIM / 128, N_DIM / 128, B_DIM), 256, SMEM_BYTES>>>(
        xt_hi, xt_lo, gw_hi, gw_lo, sNC, 0, C_DIM,
        gv_hi, gv_lo, nullptr, sCIN, N_DIM, nullptr, g_b, 0,
        nullptr, nullptr, nullptr, nullptr, nullptr, nullptr);
    // 4) S: D[m,n] = sum_ci phi[m,ci] * theta[n,ci]  -> S fp32 [B,N,N]
    gemm_kernel<<<dim3(N_DIM / 128, N_DIM / 128, B_DIM), 256, SMEM_BYTES>>>(
        ph_hi, ph_lo, th_hi, th_lo, sNCI, sNCI, CI_DIM,
        nullptr, nullptr, Sp, sNN, N_DIM, nullptr, nullptr, 1,
        nullptr, nullptr, nullptr, nullptr, nullptr, nullptr);
    // 5) softmax rows -> P hi/lo
    softmax_split<<<B_DIM * N_DIM, 256>>>();
    // 6) y: D[ci,n] = sum_m gv[ci,m] * P[n,m]  -> y [B,N,CI]
    gemm_kernel<<<dim3(N_DIM / 128, CI_DIM / 128, B_DIM), 256, SMEM_BYTES>>>(
        gv_hi, gv_lo, P_hi, P_lo, sCIN, sNN, N_DIM,
        y_hi, y_lo, nullptr, sNCI, CI_DIM, nullptr, nullptr, 0,
        nullptr, nullptr, nullptr, nullptr, nullptr, nullptr);
    // 7) out: D[n,c] = sum_ci y[n,ci] * ww[c,ci], BN + residual
    gemm_kernel<<<dim3(C_DIM / 128, N_DIM / 128, B_DIM), 256, SMEM_BYTES>>>(
        y_hi, y_lo, ww_hi, ww_lo, sNCI, 0, CI_DIM,
        nullptr, nullptr, out, sCN, N_DIM, nullptr, nullptr, 2,
        bn_gamma, bn_beta, bn_mean, bn_var, w_b, x);
}

// round 12
// speedup vs baseline: 1.3094x; 1.3094x over previous
#include <cuda_runtime.h>
#include <cuda_bf16.h>
#include <stdint.h>
#include <math.h>

#define C_DIM  1024
#define CI_DIM 256
#define B_DIM  16
#define N_DIM  2048
#define BN_EPS 1e-5f

typedef __nv_bfloat16 bf16;

// ---------------------------------------------------------------------------
// Static device scratch (hi/lo split-precision planes)
// ---------------------------------------------------------------------------
__device__ bf16 g_xT_hi[(size_t)B_DIM * N_DIM * C_DIM];
__device__ bf16 g_xT_lo[(size_t)B_DIM * N_DIM * C_DIM];
__device__ bf16 g_tw_hi[CI_DIM * C_DIM], g_tw_lo[CI_DIM * C_DIM];
__device__ bf16 g_pw_hi[CI_DIM * C_DIM], g_pw_lo[CI_DIM * C_DIM];
__device__ bf16 g_gw_hi[CI_DIM * C_DIM], g_gw_lo[CI_DIM * C_DIM];
__device__ bf16 g_ww_hi[C_DIM * CI_DIM], g_ww_lo[C_DIM * CI_DIM];
__device__ bf16 g_th_hi[(size_t)B_DIM * N_DIM * CI_DIM], g_th_lo[(size_t)B_DIM * N_DIM * CI_DIM];
__device__ bf16 g_ph_hi[(size_t)B_DIM * N_DIM * CI_DIM], g_ph_lo[(size_t)B_DIM * N_DIM * CI_DIM];
__device__ bf16 g_gv_hi[(size_t)B_DIM * CI_DIM * N_DIM], g_gv_lo[(size_t)B_DIM * CI_DIM * N_DIM];
__device__ float g_S[(size_t)B_DIM * N_DIM * N_DIM];
__device__ bf16 g_P_hi[(size_t)B_DIM * N_DIM * N_DIM], g_P_lo[(size_t)B_DIM * N_DIM * N_DIM];
__device__ bf16 g_y_hi[(size_t)B_DIM * N_DIM * CI_DIM], g_y_lo[(size_t)B_DIM * N_DIM * CI_DIM];

// ---------------------------------------------------------------------------
// PTX helpers (sm_80+ base features only — target is plain sm_103)
// ---------------------------------------------------------------------------
__device__ __forceinline__ uint32_t smem_u32(const void* p) {
    uint32_t a;
    asm("{ .reg .u64 t; cvta.to.shared.u64 t, %1; cvt.u32.u64 %0, t; }" : "=r"(a) : "l"(p));
    return a;
}
__device__ __forceinline__ void cpasync16(uint32_t s, const void* g) {
    asm volatile("cp.async.cg.shared.global [%0], [%1], 16;\n" :: "r"(s), "l"(g));
}
#define CP_COMMIT() asm volatile("cp.async.commit_group;" ::: "memory")
#define CP_WAIT(n)  asm volatile("cp.async.wait_group %0;" :: "n"(n) : "memory")

#define LDSM4(r0, r1, r2, r3, addr) \
    asm volatile("ldmatrix.sync.aligned.m8n8.x4.shared.b16 {%0,%1,%2,%3}, [%4];" \
        : "=r"(r0), "=r"(r1), "=r"(r2), "=r"(r3) : "r"(addr))

#define MMA_BF16(d, a, b) \
    asm volatile("mma.sync.aligned.m16n8k16.row.col.f32.bf16.bf16.f32 " \
        "{%0,%1,%2,%3}, {%4,%5,%6,%7}, {%8,%9}, {%0,%1,%2,%3};" \
        : "+f"((d)[0]), "+f"((d)[1]), "+f"((d)[2]), "+f"((d)[3]) \
        : "r"((a)[0]), "r"((a)[1]), "r"((a)[2]), "r"((a)[3]), "r"((b)[0]), "r"((b)[1]))

// ---------------------------------------------------------------------------
// Generic split-bf16 HMMA GEMM:  D[i,j] = sum_k A[i,k]*B[j,k]
//   CTA tile 128x128, K-chunk 32, 2-stage cp.async.
//   16 warps (512 thr), warp grid 4x4, warp tile 32x32.
//   Stage layout (64B rows, XOR-4 swizzle on 16B chunks):
//     Ah @0, Al @8192, Bh @16384, Bl @24576; stage stride 32768.
//   mode 0: bf16 hi/lo out (+optional bias_i[i], bias_j[j]), out[j*ldo+i]
//   mode 1: fp32 out[j*ldo+i]
//   mode 2: fp32 out = D*inv[j] + shift[j] + xres  (BN + residual)
// ---------------------------------------------------------------------------
#define NTHR 512
#define STAGE_BYTES 32768
#define EPI_PITCH   132
#define SMEM_BYTES  (128 * EPI_PITCH * 4 + 512)   // 68096 >= 2*STAGE_BYTES

__device__ __forceinline__ uint32_t swz(int row, int ch) {
    return (uint32_t)(row * 64 + ((ch ^ (row & 3)) << 4));
}
__device__ __forceinline__ uint32_t ldsm_addr(uint32_t pbase, int rbase, int c0, int lane) {
    const int r = rbase + (lane & 15);
    const int c = c0 + (lane >> 4);
    return pbase + swz(r, c);
}

__device__ __forceinline__ void fill_stage(uint32_t sbase,
    const bf16* __restrict__ Ah, const bf16* __restrict__ Al,
    const bf16* __restrict__ Bh, const bf16* __restrict__ Bl,
    int i0, int j0, int koff, int K)
{
    const int e = threadIdx.x;          // 0..511 == one 16B chunk per plane
    const int row = e >> 2;             // 0..127
    const int ch  = e & 3;              // 16B chunk within 64B row
    const uint32_t so = swz(row, ch);
    const size_t ka = (size_t)(i0 + row) * K + koff + ch * 8;
    const size_t kb = (size_t)(j0 + row) * K + koff + ch * 8;
    cpasync16(sbase + so,         Ah + ka);
    cpasync16(sbase + 8192 + so,  Al + ka);
    cpasync16(sbase + 16384 + so, Bh + kb);
    cpasync16(sbase + 24576 + so, Bl + kb);
}

__global__ __launch_bounds__(NTHR, 1)
void gemm_kernel(const bf16* __restrict__ Ahi, const bf16* __restrict__ Alo,
                 const bf16* __restrict__ Bhi, const bf16* __restrict__ Blo,
                 long long sA, long long sB, int K,
                 bf16* __restrict__ Ohi, bf16* __restrict__ Olo, float* __restrict__ O32,
                 long long sO, int ldo,
                 const float* __restrict__ bias_i, const float* __restrict__ bias_j,
                 int mode,
                 const float* __restrict__ gamma, const float* __restrict__ beta,
                 const float* __restrict__ mean, const float* __restrict__ var,
                 const float* __restrict__ wbias, const float* __restrict__ xres)
{
    extern __shared__ char dsm[];
    const int t = threadIdx.x, lane = t & 31, wid = t >> 5;
    const int wm = wid >> 2, wn = wid & 3;       // 4 x 4 warp grid, 32x32 tiles
    const int b = blockIdx.z;
    const int i0 = blockIdx.y * 128, j0 = blockIdx.x * 128;

    const bf16* Ah = Ahi + (size_t)b * sA;
    const bf16* Al = Alo + (size_t)b * sA;
    const bf16* Bh = Bhi + (size_t)b * sB;
    const bf16* Bl = Blo + (size_t)b * sB;

    const uint32_t sb = smem_u32(dsm);

    float acc[2][4][4] = {};

    const int nk = K >> 5;   // 32-wide K chunks

    fill_stage(sb, Ah, Al, Bh, Bl, i0, j0, 0, K);
    CP_COMMIT();

    for (int k = 0; k < nk; k++) {
        if (k + 1 < nk) {
            fill_stage(sb + ((k + 1) & 1) * STAGE_BYTES, Ah, Al, Bh, Bl, i0, j0, (k + 1) << 5, K);
            CP_COMMIT();
            CP_WAIT(1);
        } else {
            CP_WAIT(0);
        }
        __syncthreads();

        const uint32_t base = sb + (k & 1) * STAGE_BYTES;
#pragma unroll
        for (int ks = 0; ks < 2; ks++) {
            const int c0 = ks * 2;
            uint32_t ah[2][4], al[2][4], bh[4][2], bl[4][2];
#pragma unroll
            for (int mi = 0; mi < 2; mi++) {
                const int rb = wm * 32 + mi * 16;
                LDSM4(ah[mi][0], ah[mi][1], ah[mi][2], ah[mi][3], ldsm_addr(base,        rb, c0, lane));
                LDSM4(al[mi][0], al[mi][1], al[mi][2], al[mi][3], ldsm_addr(base + 8192, rb, c0, lane));
            }
#pragma unroll
            for (int nip = 0; nip < 2; nip++) {
                const int rb = wn * 32 + nip * 16;
                uint32_t r0, r1, r2, r3;
                LDSM4(r0, r1, r2, r3, ldsm_addr(base + 16384, rb, c0, lane));
                bh[nip * 2][0] = r0; bh[nip * 2 + 1][0] = r1;
                bh[nip * 2][1] = r2; bh[nip * 2 + 1][1] = r3;
                LDSM4(r0, r1, r2, r3, ldsm_addr(base + 24576, rb, c0, lane));
                bl[nip * 2][0] = r0; bl[nip * 2 + 1][0] = r1;
                bl[nip * 2][1] = r2; bl[nip * 2 + 1][1] = r3;
            }
#pragma unroll
            for (int mi = 0; mi < 2; mi++)
#pragma unroll
                for (int ni = 0; ni < 4; ni++) {
                    MMA_BF16(acc[mi][ni], ah[mi], bh[ni]);
                    MMA_BF16(acc[mi][ni], ah[mi], bl[ni]);
                    MMA_BF16(acc[mi][ni], al[mi], bh[ni]);
                }
        }
        __syncthreads();
    }

    // ---- epilogue: stage fp32 tile through smem (pitch 132), coalesced out ----
    float* sf = (float*)dsm;
    {
        const int r0 = lane >> 2;
        const int cpair = (lane & 3) << 1;
#pragma unroll
        for (int mi = 0; mi < 2; mi++)
#pragma unroll
            for (int ni = 0; ni < 4; ni++) {
                const int il = wm * 32 + mi * 16 + r0;
                const int jl = wn * 32 + ni * 8 + cpair;
                sf[jl * EPI_PITCH + il]           = acc[mi][ni][0];
                sf[(jl + 1) * EPI_PITCH + il]     = acc[mi][ni][1];
                sf[jl * EPI_PITCH + il + 8]       = acc[mi][ni][2];
                sf[(jl + 1) * EPI_PITCH + il + 8] = acc[mi][ni][3];
            }
    }
    __syncthreads();

#pragma unroll 4
    for (int rep = 0; rep < 32; rep++) {
        const int idx = rep * NTHR + t;
        const int jl = idx >> 7, il = idx & 127;
        float v = sf[jl * EPI_PITCH + il];
        const int i = i0 + il;
        const int jg = j0 + jl;
        if (mode == 0) {
            if (bias_i) v += bias_i[i];
            if (bias_j) v += bias_j[jg];
            const bf16 h = __float2bfloat16(v);
            const float lo = v - __bfloat162float(h);
            const size_t a = (size_t)b * sO + (size_t)jg * ldo + i;
            Ohi[a] = h;
            Olo[a] = __float2bfloat16(lo);
        } else if (mode == 1) {
            O32[(size_t)b * sO + (size_t)jg * ldo + i] = v;
        } else {
            const float iv = gamma[jg] * rsqrtf(var[jg] + BN_EPS);
            const float sh = beta[jg] + (wbias[jg] - mean[jg]) * iv;
            const size_t a = (size_t)b * sO + (size_t)jg * ldo + i;
            O32[a] = v * iv + sh + xres[a];
        }
    }
}

// ---------------------------------------------------------------------------
// All 4 weight tensors split in one launch
// ---------------------------------------------------------------------------
#define W3_ELEMS (CI_DIM * C_DIM)
__global__ void conv_split4(const float* __restrict__ tw, const float* __restrict__ pw,
                            const float* __restrict__ gw, const float* __restrict__ ww)
{
    const int idx = blockIdx.x * 256 + threadIdx.x;
    const int sel = idx / W3_ELEMS;
    const int off = idx - sel * W3_ELEMS;
    const float* in = (sel == 0) ? tw : (sel == 1) ? pw : (sel == 2) ? gw : ww;
    bf16* hi = (sel == 0) ? g_tw_hi : (sel == 1) ? g_pw_hi : (sel == 2) ? g_gw_hi : g_ww_hi;
    bf16* lo = (sel == 0) ? g_tw_lo : (sel == 1) ? g_pw_lo : (sel == 2) ? g_gw_lo : g_ww_lo;
    const float v = in[off];
    const bf16 h = __float2bfloat16(v);
    hi[off] = h;
    lo[off] = __float2bfloat16(v - __bfloat162float(h));
}

// ---------------------------------------------------------------------------
// x [B,C,N] fp32 -> xT [B,N,C] bf16 hi/lo  (32x32 smem transpose)
// ---------------------------------------------------------------------------
__global__ __launch_bounds__(256)
void transpose_split(const float* __restrict__ x)
{
    __shared__ float tb[32][33];
    const int b = blockIdx.z;
    const int c0 = blockIdx.y * 32;
    const int n0 = blockIdx.x * 32;
    const int tx = threadIdx.x & 31, ty = threadIdx.x >> 5;
#pragma unroll
    for (int it = 0; it < 4; it++)
        tb[ty + it * 8][tx] = x[((size_t)b * C_DIM + c0 + ty + it * 8) * N_DIM + n0 + tx];
    __syncthreads();
#pragma unroll
    for (int it = 0; it < 4; it++) {
        const float v = tb[tx][ty + it * 8];
        const size_t a = ((size_t)b * N_DIM + n0 + ty + it * 8) * C_DIM + c0 + tx;
        const bf16 h = __float2bfloat16(v);
        g_xT_hi[a] = h;
        g_xT_lo[a] = __float2bfloat16(v - __bfloat162float(h));
    }
}

// ---------------------------------------------------------------------------
// Row softmax: S fp32 [row][2048] -> P hi/lo bf16
// ---------------------------------------------------------------------------
__global__ __launch_bounds__(256)
void softmax_split()
{
    const size_t row = (size_t)blockIdx.x * N_DIM;
    const float* __restrict__ s = g_S + row;
    __shared__ float buf[N_DIM];
    __shared__ float red[8];
    const int tid = threadIdx.x, lane = tid & 31, warp = tid >> 5;

    float lmax = -INFINITY;
#pragma unroll
    for (int it = 0; it < N_DIM / 256; it++) {
        float v = s[tid + it * 256];
        buf[tid + it * 256] = v;
        lmax = fmaxf(lmax, v);
    }
#pragma unroll
    for (int o = 16; o; o >>= 1) lmax = fmaxf(lmax, __shfl_xor_sync(0xffffffffu, lmax, o));
    if (lane == 0) red[warp] = lmax;
    __syncthreads();
    float m = red[0];
#pragma unroll
    for (int w = 1; w < 8; w++) m = fmaxf(m, red[w]);
    __syncthreads();

    float lsum = 0.f;
#pragma unroll
    for (int it = 0; it < N_DIM / 256; it++) {
        float e = __expf(buf[tid + it * 256] - m);
        buf[tid + it * 256] = e;
        lsum += e;
    }
#pragma unroll
    for (int o = 16; o; o >>= 1) lsum += __shfl_xor_sync(0xffffffffu, lsum, o);
    if (lane == 0) red[warp] = lsum;
    __syncthreads();
    float tot = red[0];
#pragma unroll
    for (int w = 1; w < 8; w++) tot += red[w];
    const float inv = 1.f / tot;

#pragma unroll
    for (int it = 0; it < N_DIM / 256; it++) {
        const int idx = tid + it * 256;
        const float p = buf[idx] * inv;
        const bf16 h = __float2bfloat16(p);
        g_P_hi[row + idx] = h;
        g_P_lo[row + idx] = __float2bfloat16(p - __bfloat162float(h));
    }
}

// ---------------------------------------------------------------------------
// Launch
// ---------------------------------------------------------------------------
extern "C" void kernel_launch(void* const* d_in, const int* in_sizes, int n_in,
                              void* d_out, int out_size)
{
    const float* x        = (const float*)d_in[0];
    const float* theta_w  = (const float*)d_in[1];
    const float* theta_b  = (const float*)d_in[2];
    const float* phi_w    = (const float*)d_in[3];
    const float* phi_b    = (const float*)d_in[4];
    const float* g_w      = (const float*)d_in[5];
    const float* g_b      = (const float*)d_in[6];
    const float* w_w      = (const float*)d_in[7];
    const float* w_b      = (const float*)d_in[8];
    const float* bn_gamma = (const float*)d_in[9];
    const float* bn_beta  = (const float*)d_in[10];
    const float* bn_mean  = (const float*)d_in[11];
    const float* bn_var   = (const float*)d_in[12];
    float* out = (float*)d_out;

    cudaFuncSetAttribute(gemm_kernel, cudaFuncAttributeMaxDynamicSharedMemorySize, SMEM_BYTES);

    bf16 *xt_hi, *xt_lo, *tw_hi, *tw_lo, *pw_hi, *pw_lo, *gw_hi, *gw_lo, *ww_hi, *ww_lo;
    bf16 *th_hi, *th_lo, *ph_hi, *ph_lo, *gv_hi, *gv_lo, *P_hi, *P_lo, *y_hi, *y_lo;
    float* Sp;
    cudaGetSymbolAddress((void**)&xt_hi, g_xT_hi); cudaGetSymbolAddress((void**)&xt_lo, g_xT_lo);
    cudaGetSymbolAddress((void**)&tw_hi, g_tw_hi); cudaGetSymbolAddress((void**)&tw_lo, g_tw_lo);
    cudaGetSymbolAddress((void**)&pw_hi, g_pw_hi); cudaGetSymbolAddress((void**)&pw_lo, g_pw_lo);
    cudaGetSymbolAddress((void**)&gw_hi, g_gw_hi); cudaGetSymbolAddress((void**)&gw_lo, g_gw_lo);
    cudaGetSymbolAddress((void**)&ww_hi, g_ww_hi); cudaGetSymbolAddress((void**)&ww_lo, g_ww_lo);
    cudaGetSymbolAddress((void**)&th_hi, g_th_hi); cudaGetSymbolAddress((void**)&th_lo, g_th_lo);
    cudaGetSymbolAddress((void**)&ph_hi, g_ph_hi); cudaGetSymbolAddress((void**)&ph_lo, g_ph_lo);
    cudaGetSymbolAddress((void**)&gv_hi, g_gv_hi); cudaGetSymbolAddress((void**)&gv_lo, g_gv_lo);
    cudaGetSymbolAddress((void**)&P_hi,  g_P_hi);  cudaGetSymbolAddress((void**)&P_lo,  g_P_lo);
    cudaGetSymbolAddress((void**)&y_hi,  g_y_hi);  cudaGetSymbolAddress((void**)&y_lo,  g_y_lo);
    cudaGetSymbolAddress((void**)&Sp,    g_S);

    // 0) weight splits (one launch) + x transpose/split
    conv_split4<<<4 * W3_ELEMS / 256, 256>>>(theta_w, phi_w, g_w, w_w);
    transpose_split<<<dim3(N_DIM / 32, C_DIM / 32, B_DIM), 256>>>(x);

    const long long sNC  = (long long)N_DIM * C_DIM;
    const long long sNCI = (long long)N_DIM * CI_DIM;
    const long long sCIN = (long long)CI_DIM * N_DIM;
    const long long sNN  = (long long)N_DIM * N_DIM;
    const long long sCN  = (long long)C_DIM * N_DIM;

    // 1) theta: D[o,n] = sum_c tw[o,c] * xT[n,c]  -> th [B,N,CI]
    gemm_kernel<<<dim3(N_DIM / 128, CI_DIM / 128, B_DIM), NTHR, SMEM_BYTES>>>(
        tw_hi, tw_lo, xt_hi, xt_lo, 0, sNC, C_DIM,
        th_hi, th_lo, nullptr, sNCI, CI_DIM, theta_b, nullptr, 0,
        nullptr, nullptr, nullptr, nullptr, nullptr, nullptr);
    // 2) phi
    gemm_kernel<<<dim3(N_DIM / 128, CI_DIM / 128, B_DIM), NTHR, SMEM_BYTES>>>(
        pw_hi, pw_lo, xt_hi, xt_lo, 0, sNC, C_DIM,
        ph_hi, ph_lo, nullptr, sNCI, CI_DIM, phi_b, nullptr, 0,
        nullptr, nullptr, nullptr, nullptr, nullptr, nullptr);
    // 3) g: D[n,ci] = sum_c xT[n,c] * gw[ci,c]  -> gv [B,CI,N]
    gemm_kernel<<<dim3(CI_DIM / 128, N_DIM / 128, B_DIM), NTHR, SMEM_BYTES>>>(
        xt_hi, xt_lo, gw_hi, gw_lo, sNC, 0, C_DIM,
        gv_hi, gv_lo, nullptr, sCIN, N_DIM, nullptr, g_b, 0,
        nullptr, nullptr, nullptr, nullptr, nullptr, nullptr);
    // 4) S: D[m,n] = sum_ci phi[m,ci] * theta[n,ci]  -> S fp32 [B,N,N]
    gemm_kernel<<<dim3(N_DIM / 128, N_DIM / 128, B_DIM), NTHR, SMEM_BYTES>>>(
        ph_hi, ph_lo, th_hi, th_lo, sNCI, sNCI, CI_DIM,
        nullptr, nullptr, Sp, sNN, N_DIM, nullptr, nullptr, 1,
        nullptr, nullptr, nullptr, nullptr, nullptr, nullptr);
    // 5) softmax rows -> P hi/lo
    softmax_split<<<B_DIM * N_DIM, 256>>>();
    // 6) y: D[ci,n] = sum_m gv[ci,m] * P[n,m]  -> y [B,N,CI]
    gemm_kernel<<<dim3(N_DIM / 128, CI_DIM / 128, B_DIM), NTHR, SMEM_BYTES>>>(
        gv_hi, gv_lo, P_hi, P_lo, sCIN, sNN, N_DIM,
        y_hi, y_lo, nullptr, sNCI, CI_DIM, nullptr, nullptr, 0,
        nullptr, nullptr, nullptr, nullptr, nullptr, nullptr);
    // 7) out: D[n,c] = sum_ci y[n,ci] * ww[c,ci], BN + residual
    gemm_kernel<<<dim3(C_DIM / 128, N_DIM / 128, B_DIM), NTHR, SMEM_BYTES>>>(
        y_hi, y_lo, ww_hi, ww_lo, sNCI, 0, CI_DIM,
        nullptr, nullptr, out, sCN, N_DIM, nullptr, nullptr, 2,
        bn_gamma, bn_beta, bn_mean, bn_var, w_b, x);
}

// round 14
// speedup vs baseline: 1.5554x; 1.1879x over previous
#include <cuda_runtime.h>
#include <cuda_bf16.h>
#include <stdint.h>
#include <math.h>

#define C_DIM  1024
#define CI_DIM 256
#define B_DIM  16
#define N_DIM  2048
#define BN_EPS 1e-5f

typedef __nv_bfloat16 bf16;

// ---------------------------------------------------------------------------
// Static device scratch (hi/lo split-precision planes)
// ---------------------------------------------------------------------------
__device__ bf16 g_xT_hi[(size_t)B_DIM * N_DIM * C_DIM];
__device__ bf16 g_xT_lo[(size_t)B_DIM * N_DIM * C_DIM];
__device__ bf16 g_tw_hi[CI_DIM * C_DIM], g_tw_lo[CI_DIM * C_DIM];
__device__ bf16 g_pw_hi[CI_DIM * C_DIM], g_pw_lo[CI_DIM * C_DIM];
__device__ bf16 g_gw_hi[CI_DIM * C_DIM], g_gw_lo[CI_DIM * C_DIM];
__device__ bf16 g_ww_hi[C_DIM * CI_DIM], g_ww_lo[C_DIM * CI_DIM];
__device__ bf16 g_th_hi[(size_t)B_DIM * N_DIM * CI_DIM], g_th_lo[(size_t)B_DIM * N_DIM * CI_DIM];
__device__ bf16 g_ph_hi[(size_t)B_DIM * N_DIM * CI_DIM], g_ph_lo[(size_t)B_DIM * N_DIM * CI_DIM];
__device__ bf16 g_gv_hi[(size_t)B_DIM * CI_DIM * N_DIM], g_gv_lo[(size_t)B_DIM * CI_DIM * N_DIM];
__device__ float g_S[(size_t)B_DIM * N_DIM * N_DIM];
__device__ bf16 g_P_hi[(size_t)B_DIM * N_DIM * N_DIM], g_P_lo[(size_t)B_DIM * N_DIM * N_DIM];
__device__ bf16 g_y_hi[(size_t)B_DIM * N_DIM * CI_DIM], g_y_lo[(size_t)B_DIM * N_DIM * CI_DIM];

// ---------------------------------------------------------------------------
// PTX helpers (sm_80+ base features only — target is plain sm_103)
// ---------------------------------------------------------------------------
__device__ __forceinline__ uint32_t smem_u32(const void* p) {
    uint32_t a;
    asm("{ .reg .u64 t; cvta.to.shared.u64 t, %1; cvt.u32.u64 %0, t; }" : "=r"(a) : "l"(p));
    return a;
}
__device__ __forceinline__ void cpasync16(uint32_t s, const void* g) {
    asm volatile("cp.async.cg.shared.global [%0], [%1], 16;\n" :: "r"(s), "l"(g));
}
#define CP_COMMIT() asm volatile("cp.async.commit_group;" ::: "memory")
#define CP_WAIT(n)  asm volatile("cp.async.wait_group %0;" :: "n"(n) : "memory")

#define LDSM4(r0, r1, r2, r3, addr) \
    asm volatile("ldmatrix.sync.aligned.m8n8.x4.shared.b16 {%0,%1,%2,%3}, [%4];" \
        : "=r"(r0), "=r"(r1), "=r"(r2), "=r"(r3) : "r"(addr))

#define MMA_BF16(d, a, b) \
    asm volatile("mma.sync.aligned.m16n8k16.row.col.f32.bf16.bf16.f32 " \
        "{%0,%1,%2,%3}, {%4,%5,%6,%7}, {%8,%9}, {%0,%1,%2,%3};" \
        : "+f"((d)[0]), "+f"((d)[1]), "+f"((d)[2]), "+f"((d)[3]) \
        : "r"((a)[0]), "r"((a)[1]), "r"((a)[2]), "r"((a)[3]), "r"((b)[0]), "r"((b)[1]))

// ---------------------------------------------------------------------------
// Generic split-bf16 HMMA GEMM:  D[i,j] = sum_k A[i,k]*B[j,k]
//   CTA tile 128(i) x 64(j), K-chunk 32, 2-stage cp.async.
//   8 warps (256 thr), warp grid 4(i) x 2(j), warp tile 32x32.
//   Targets 3 CTAs/SM (regs<=85, smem 48KB) so independent CTAs cover
//   each other's barrier/fill bubbles.
//   Stage layout (64B rows, XOR-4 swizzle on 16B chunks):
//     Ah @0 (8KB), Al @8192, Bh @16384 (4KB), Bl @20480; stride 24576.
//   mode 0: bf16 hi/lo out (+optional bias_i[i], bias_j[j]), out[j*ldo+i]
//   mode 1: fp32 out[j*ldo+i]
//   mode 2: fp32 out = D*inv[j] + shift[j] + xres  (BN + residual)
// ---------------------------------------------------------------------------
#define NTHR 256
#define STAGE_BYTES 24576
#define EPI_PITCH   132
#define SMEM_BYTES  49152    // 2 stages; epilogue staging (64*132*4=33792) reuses it

__device__ __forceinline__ uint32_t swz(int row, int ch) {
    return (uint32_t)(row * 64 + ((ch ^ (row & 3)) << 4));
}
__device__ __forceinline__ uint32_t ldsm_addr(uint32_t pbase, int rbase, int c0, int lane) {
    const int r = rbase + (lane & 15);
    const int c = c0 + (lane >> 4);
    return pbase + swz(r, c);
}

__device__ __forceinline__ void fill_stage(uint32_t sbase,
    const bf16* __restrict__ Ah, const bf16* __restrict__ Al,
    const bf16* __restrict__ Bh, const bf16* __restrict__ Bl,
    int i0, int j0, int koff, int K)
{
    const int t = threadIdx.x;
    // A planes: 128 rows x 4 chunks = 512 chunks, 2 per thread
#pragma unroll
    for (int r = 0; r < 2; r++) {
        const int e = t + r * 256;
        const int row = e >> 2, ch = e & 3;
        const uint32_t so = swz(row, ch);
        const size_t ka = (size_t)(i0 + row) * K + koff + ch * 8;
        cpasync16(sbase + so,        Ah + ka);
        cpasync16(sbase + 8192 + so, Al + ka);
    }
    // B planes: 64 rows x 4 chunks = 256 chunks, 1 per thread
    {
        const int row = t >> 2, ch = t & 3;
        const uint32_t so = swz(row, ch);
        const size_t kb = (size_t)(j0 + row) * K + koff + ch * 8;
        cpasync16(sbase + 16384 + so, Bh + kb);
        cpasync16(sbase + 20480 + so, Bl + kb);
    }
}

__global__ __launch_bounds__(NTHR, 3)
void gemm_kernel(const bf16* __restrict__ Ahi, const bf16* __restrict__ Alo,
                 const bf16* __restrict__ Bhi, const bf16* __restrict__ Blo,
                 long long sA, long long sB, int K,
                 bf16* __restrict__ Ohi, bf16* __restrict__ Olo, float* __restrict__ O32,
                 long long sO, int ldo,
                 const float* __restrict__ bias_i, const float* __restrict__ bias_j,
                 int mode,
                 const float* __restrict__ gamma, const float* __restrict__ beta,
                 const float* __restrict__ mean, const float* __restrict__ var,
                 const float* __restrict__ wbias, const float* __restrict__ xres)
{
    extern __shared__ char dsm[];
    const int t = threadIdx.x, lane = t & 31, wid = t >> 5;
    const int wm = wid >> 1, wn = wid & 1;       // 4 x 2 warp grid, 32x32 tiles
    const int b = blockIdx.z;
    const int i0 = blockIdx.y * 128, j0 = blockIdx.x * 64;

    const bf16* Ah = Ahi + (size_t)b * sA;
    const bf16* Al = Alo + (size_t)b * sA;
    const bf16* Bh = Bhi + (size_t)b * sB;
    const bf16* Bl = Blo + (size_t)b * sB;

    const uint32_t sb = smem_u32(dsm);

    float acc[2][4][4] = {};

    const int nk = K >> 5;   // 32-wide K chunks

    fill_stage(sb, Ah, Al, Bh, Bl, i0, j0, 0, K);
    CP_COMMIT();

    for (int k = 0; k < nk; k++) {
        if (k + 1 < nk) {
            fill_stage(sb + ((k + 1) & 1) * STAGE_BYTES, Ah, Al, Bh, Bl, i0, j0, (k + 1) << 5, K);
            CP_COMMIT();
            CP_WAIT(1);
        } else {
            CP_WAIT(0);
        }
        __syncthreads();

        const uint32_t base = sb + (k & 1) * STAGE_BYTES;
#pragma unroll
        for (int ks = 0; ks < 2; ks++) {
            const int c0 = ks * 2;
            uint32_t ah[2][4], al[2][4], bh[4][2], bl[4][2];
#pragma unroll
            for (int mi = 0; mi < 2; mi++) {
                const int rb = wm * 32 + mi * 16;
                LDSM4(ah[mi][0], ah[mi][1], ah[mi][2], ah[mi][3], ldsm_addr(base,        rb, c0, lane));
                LDSM4(al[mi][0], al[mi][1], al[mi][2], al[mi][3], ldsm_addr(base + 8192, rb, c0, lane));
            }
#pragma unroll
            for (int nip = 0; nip < 2; nip++) {
                const int rb = wn * 32 + nip * 16;
                uint32_t r0, r1, r2, r3;
                LDSM4(r0, r1, r2, r3, ldsm_addr(base + 16384, rb, c0, lane));
                bh[nip * 2][0] = r0; bh[nip * 2 + 1][0] = r1;
                bh[nip * 2][1] = r2; bh[nip * 2 + 1][1] = r3;
                LDSM4(r0, r1, r2, r3, ldsm_addr(base + 20480, rb, c0, lane));
                bl[nip * 2][0] = r0; bl[nip * 2 + 1][0] = r1;
                bl[nip * 2][1] = r2; bl[nip * 2 + 1][1] = r3;
            }
#pragma unroll
            for (int mi = 0; mi < 2; mi++)
#pragma unroll
                for (int ni = 0; ni < 4; ni++) {
                    MMA_BF16(acc[mi][ni], ah[mi], bh[ni]);
                    MMA_BF16(acc[mi][ni], ah[mi], bl[ni]);
                    MMA_BF16(acc[mi][ni], al[mi], bh[ni]);
                }
        }
        __syncthreads();
    }

    // ---- epilogue: stage fp32 tile (128 x 64) through smem, coalesced out ----
    float* sf = (float*)dsm;
    {
        const int r0 = lane >> 2;
        const int cpair = (lane & 3) << 1;
#pragma unroll
        for (int mi = 0; mi < 2; mi++)
#pragma unroll
            for (int ni = 0; ni < 4; ni++) {
                const int il = wm * 32 + mi * 16 + r0;
                const int jl = wn * 32 + ni * 8 + cpair;
                sf[jl * EPI_PITCH + il]           = acc[mi][ni][0];
                sf[(jl + 1) * EPI_PITCH + il]     = acc[mi][ni][1];
                sf[jl * EPI_PITCH + il + 8]       = acc[mi][ni][2];
                sf[(jl + 1) * EPI_PITCH + il + 8] = acc[mi][ni][3];
            }
    }
    __syncthreads();

#pragma unroll 4
    for (int rep = 0; rep < 32; rep++) {
        const int idx = rep * NTHR + t;
        const int jl = idx >> 7, il = idx & 127;
        float v = sf[jl * EPI_PITCH + il];
        const int i = i0 + il;
        const int jg = j0 + jl;
        if (mode == 0) {
            if (bias_i) v += bias_i[i];
            if (bias_j) v += bias_j[jg];
            const bf16 h = __float2bfloat16(v);
            const float lo = v - __bfloat162float(h);
            const size_t a = (size_t)b * sO + (size_t)jg * ldo + i;
            Ohi[a] = h;
            Olo[a] = __float2bfloat16(lo);
        } else if (mode == 1) {
            O32[(size_t)b * sO + (size_t)jg * ldo + i] = v;
        } else {
            const float iv = gamma[jg] * rsqrtf(var[jg] + BN_EPS);
            const float sh = beta[jg] + (wbias[jg] - mean[jg]) * iv;
            const size_t a = (size_t)b * sO + (size_t)jg * ldo + i;
            O32[a] = v * iv + sh + xres[a];
        }
    }
}

// ---------------------------------------------------------------------------
// All 4 weight tensors split in one launch
// ---------------------------------------------------------------------------
#define W3_ELEMS (CI_DIM * C_DIM)
__global__ void conv_split4(const float* __restrict__ tw, const float* __restrict__ pw,
                            const float* __restrict__ gw, const float* __restrict__ ww)
{
    const int idx = blockIdx.x * 256 + threadIdx.x;
    const int sel = idx / W3_ELEMS;
    const int off = idx - sel * W3_ELEMS;
    const float* in = (sel == 0) ? tw : (sel == 1) ? pw : (sel == 2) ? gw : ww;
    bf16* hi = (sel == 0) ? g_tw_hi : (sel == 1) ? g_pw_hi : (sel == 2) ? g_gw_hi : g_ww_hi;
    bf16* lo = (sel == 0) ? g_tw_lo : (sel == 1) ? g_pw_lo : (sel == 2) ? g_gw_lo : g_ww_lo;
    const float v = in[off];
    const bf16 h = __float2bfloat16(v);
    hi[off] = h;
    lo[off] = __float2bfloat16(v - __bfloat162float(h));
}

// ---------------------------------------------------------------------------
// x [B,C,N] fp32 -> xT [B,N,C] bf16 hi/lo  (32x32 smem transpose)
// ---------------------------------------------------------------------------
__global__ __launch_bounds__(256)
void transpose_split(const float* __restrict__ x)
{
    __shared__ float tb[32][33];
    const int b = blockIdx.z;
    const int c0 = blockIdx.y * 32;
    const int n0 = blockIdx.x * 32;
    const int tx = threadIdx.x & 31, ty = threadIdx.x >> 5;
#pragma unroll
    for (int it = 0; it < 4; it++)
        tb[ty + it * 8][tx] = x[((size_t)b * C_DIM + c0 + ty + it * 8) * N_DIM + n0 + tx];
    __syncthreads();
#pragma unroll
    for (int it = 0; it < 4; it++) {
        const float v = tb[tx][ty + it * 8];
        const size_t a = ((size_t)b * N_DIM + n0 + ty + it * 8) * C_DIM + c0 + tx;
        const bf16 h = __float2bfloat16(v);
        g_xT_hi[a] = h;
        g_xT_lo[a] = __float2bfloat16(v - __bfloat162float(h));
    }
}

// ---------------------------------------------------------------------------
// Row softmax: S fp32 [row][2048] -> P hi/lo bf16
// ---------------------------------------------------------------------------
__global__ __launch_bounds__(256)
void softmax_split()
{
    const size_t row = (size_t)blockIdx.x * N_DIM;
    const float* __restrict__ s = g_S + row;
    __shared__ float buf[N_DIM];
    __shared__ float red[8];
    const int tid = threadIdx.x, lane = tid & 31, warp = tid >> 5;

    float lmax = -INFINITY;
#pragma unroll
    for (int it = 0; it < N_DIM / 256; it++) {
        float v = s[tid + it * 256];
        buf[tid + it * 256] = v;
        lmax = fmaxf(lmax, v);
    }
#pragma unroll
    for (int o = 16; o; o >>= 1) lmax = fmaxf(lmax, __shfl_xor_sync(0xffffffffu, lmax, o));
    if (lane == 0) red[warp] = lmax;
    __syncthreads();
    float m = red[0];
#pragma unroll
    for (int w = 1; w < 8; w++) m = fmaxf(m, red[w]);
    __syncthreads();

    float lsum = 0.f;
#pragma unroll
    for (int it = 0; it < N_DIM / 256; it++) {
        float e = __expf(buf[tid + it * 256] - m);
        buf[tid + it * 256] = e;
        lsum += e;
    }
#pragma unroll
    for (int o = 16; o; o >>= 1) lsum += __shfl_xor_sync(0xffffffffu, lsum, o);
    if (lane == 0) red[warp] = lsum;
    __syncthreads();
    float tot = red[0];
#pragma unroll
    for (int w = 1; w < 8; w++) tot += red[w];
    const float inv = 1.f / tot;

#pragma unroll
    for (int it = 0; it < N_DIM / 256; it++) {
        const int idx = tid + it * 256;
        const float p = buf[idx] * inv;
        const bf16 h = __float2bfloat16(p);
        g_P_hi[row + idx] = h;
        g_P_lo[row + idx] = __float2bfloat16(p - __bfloat162float(h));
    }
}

// ---------------------------------------------------------------------------
// Launch
// ---------------------------------------------------------------------------
extern "C" void kernel_launch(void* const* d_in, const int* in_sizes, int n_in,
                              void* d_out, int out_size)
{
    const float* x        = (const float*)d_in[0];
    const float* theta_w  = (const float*)d_in[1];
    const float* theta_b  = (const float*)d_in[2];
    const float* phi_w    = (const float*)d_in[3];
    const float* phi_b    = (const float*)d_in[4];
    const float* g_w      = (const float*)d_in[5];
    const float* g_b      = (const float*)d_in[6];
    const float* w_w      = (const float*)d_in[7];
    const float* w_b      = (const float*)d_in[8];
    const float* bn_gamma = (const float*)d_in[9];
    const float* bn_beta  = (const float*)d_in[10];
    const float* bn_mean  = (const float*)d_in[11];
    const float* bn_var   = (const float*)d_in[12];
    float* out = (float*)d_out;

    cudaFuncSetAttribute(gemm_kernel, cudaFuncAttributeMaxDynamicSharedMemorySize, SMEM_BYTES);

    bf16 *xt_hi, *xt_lo, *tw_hi, *tw_lo, *pw_hi, *pw_lo, *gw_hi, *gw_lo, *ww_hi, *ww_lo;
    bf16 *th_hi, *th_lo, *ph_hi, *ph_lo, *gv_hi, *gv_lo, *P_hi, *P_lo, *y_hi, *y_lo;
    float* Sp;
    cudaGetSymbolAddress((void**)&xt_hi, g_xT_hi); cudaGetSymbolAddress((void**)&xt_lo, g_xT_lo);
    cudaGetSymbolAddress((void**)&tw_hi, g_tw_hi); cudaGetSymbolAddress((void**)&tw_lo, g_tw_lo);
    cudaGetSymbolAddress((void**)&pw_hi, g_pw_hi); cudaGetSymbolAddress((void**)&pw_lo, g_pw_lo);
    cudaGetSymbolAddress((void**)&gw_hi, g_gw_hi); cudaGetSymbolAddress((void**)&gw_lo, g_gw_lo);
    cudaGetSymbolAddress((void**)&ww_hi, g_ww_hi); cudaGetSymbolAddress((void**)&ww_lo, g_ww_lo);
    cudaGetSymbolAddress((void**)&th_hi, g_th_hi); cudaGetSymbolAddress((void**)&th_lo, g_th_lo);
    cudaGetSymbolAddress((void**)&ph_hi, g_ph_hi); cudaGetSymbolAddress((void**)&ph_lo, g_ph_lo);
    cudaGetSymbolAddress((void**)&gv_hi, g_gv_hi); cudaGetSymbolAddress((void**)&gv_lo, g_gv_lo);
    cudaGetSymbolAddress((void**)&P_hi,  g_P_hi);  cudaGetSymbolAddress((void**)&P_lo,  g_P_lo);
    cudaGetSymbolAddress((void**)&y_hi,  g_y_hi);  cudaGetSymbolAddress((void**)&y_lo,  g_y_lo);
    cudaGetSymbolAddress((void**)&Sp,    g_S);

    // 0) weight splits (one launch) + x transpose/split
    conv_split4<<<4 * W3_ELEMS / 256, 256>>>(theta_w, phi_w, g_w, w_w);
    transpose_split<<<dim3(N_DIM / 32, C_DIM / 32, B_DIM), 256>>>(x);

    const long long sNC  = (long long)N_DIM * C_DIM;
    const long long sNCI = (long long)N_DIM * CI_DIM;
    const long long sCIN = (long long)CI_DIM * N_DIM;
    const long long sNN  = (long long)N_DIM * N_DIM;
    const long long sCN  = (long long)C_DIM * N_DIM;

    // 1) theta: D[o,n] = sum_c tw[o,c] * xT[n,c]  -> th [B,N,CI]
    gemm_kernel<<<dim3(N_DIM / 64, CI_DIM / 128, B_DIM), NTHR, SMEM_BYTES>>>(
        tw_hi, tw_lo, xt_hi, xt_lo, 0, sNC, C_DIM,
        th_hi, th_lo, nullptr, sNCI, CI_DIM, theta_b, nullptr, 0,
        nullptr, nullptr, nullptr, nullptr, nullptr, nullptr);
    // 2) phi
    gemm_kernel<<<dim3(N_DIM / 64, CI_DIM / 128, B_DIM), NTHR, SMEM_BYTES>>>(
        pw_hi, pw_lo, xt_hi, xt_lo, 0, sNC, C_DIM,
        ph_hi, ph_lo, nullptr, sNCI, CI_DIM, phi_b, nullptr, 0,
        nullptr, nullptr, nullptr, nullptr, nullptr, nullptr);
    // 3) g: D[n,ci] = sum_c xT[n,c] * gw[ci,c]  -> gv [B,CI,N]
    gemm_kernel<<<dim3(CI_DIM / 64, N_DIM / 128, B_DIM), NTHR, SMEM_BYTES>>>(
        xt_hi, xt_lo, gw_hi, gw_lo, sNC, 0, C_DIM,
        gv_hi, gv_lo, nullptr, sCIN, N_DIM, nullptr, g_b, 0,
        nullptr, nullptr, nullptr, nullptr, nullptr, nullptr);
    // 4) S: D[m,n] = sum_ci phi[m,ci] * theta[n,ci]  -> S fp32 [B,N,N]
    gemm_kernel<<<dim3(N_DIM / 64, N_DIM / 128, B_DIM), NTHR, SMEM_BYTES>>>(
        ph_hi, ph_lo, th_hi, th_lo, sNCI, sNCI, CI_DIM,
        nullptr, nullptr, Sp, sNN, N_DIM, nullptr, nullptr, 1,
        nullptr, nullptr, nullptr, nullptr, nullptr, nullptr);
    // 5) softmax rows -> P hi/lo
    softmax_split<<<B_DIM * N_DIM, 256>>>();
    // 6) y: D[ci,n] = sum_m gv[ci,m] * P[n,m]  -> y [B,N,CI]
    gemm_kernel<<<dim3(N_DIM / 64, CI_DIM / 128, B_DIM), NTHR, SMEM_BYTES>>>(
        gv_hi, gv_lo, P_hi, P_lo, sCIN, sNN, N_DIM,
        y_hi, y_lo, nullptr, sNCI, CI_DIM, nullptr, nullptr, 0,
        nullptr, nullptr, nullptr, nullptr, nullptr, nullptr);
    // 7) out: D[n,c] = sum_ci y[n,ci] * ww[c,ci], BN + residual
    gemm_kernel<<<dim3(C_DIM / 64, N_DIM / 128, B_DIM), NTHR, SMEM_BYTES>>>(
        y_hi, y_lo, ww_hi, ww_lo, sNCI, 0, CI_DIM,
        nullptr, nullptr, out, sCN, N_DIM, nullptr, nullptr, 2,
        bn_gamma, bn_beta, bn_mean, bn_var, w_b, x);
}

// round 17
// speedup vs baseline: 1.5952x; 1.0256x over previous
#include <cuda_runtime.h>
#include <cuda_bf16.h>
#include <stdint.h>
#include <math.h>

#define C_DIM  1024
#define CI_DIM 256
#define B_DIM  16
#define N_DIM  2048
#define BN_EPS 1e-5f

typedef __nv_bfloat16 bf16;

// ---------------------------------------------------------------------------
// Static device scratch (hi/lo split-precision planes)
// ---------------------------------------------------------------------------
__device__ bf16 g_xT_hi[(size_t)B_DIM * N_DIM * C_DIM];
__device__ bf16 g_xT_lo[(size_t)B_DIM * N_DIM * C_DIM];
__device__ bf16 g_tw_hi[CI_DIM * C_DIM], g_tw_lo[CI_DIM * C_DIM];
__device__ bf16 g_pw_hi[CI_DIM * C_DIM], g_pw_lo[CI_DIM * C_DIM];
__device__ bf16 g_gw_hi[CI_DIM * C_DIM], g_gw_lo[CI_DIM * C_DIM];
__device__ bf16 g_ww_hi[C_DIM * CI_DIM], g_ww_lo[C_DIM * CI_DIM];
__device__ bf16 g_th_hi[(size_t)B_DIM * N_DIM * CI_DIM], g_th_lo[(size_t)B_DIM * N_DIM * CI_DIM];
__device__ bf16 g_ph_hi[(size_t)B_DIM * N_DIM * CI_DIM], g_ph_lo[(size_t)B_DIM * N_DIM * CI_DIM];
__device__ bf16 g_gv_hi[(size_t)B_DIM * CI_DIM * N_DIM], g_gv_lo[(size_t)B_DIM * CI_DIM * N_DIM];
__device__ float g_S[(size_t)B_DIM * N_DIM * N_DIM];
__device__ bf16 g_P_hi[(size_t)B_DIM * N_DIM * N_DIM], g_P_lo[(size_t)B_DIM * N_DIM * N_DIM];
__device__ bf16 g_y_hi[(size_t)B_DIM * N_DIM * CI_DIM], g_y_lo[(size_t)B_DIM * N_DIM * CI_DIM];

// ---------------------------------------------------------------------------
// PTX helpers (sm_80+ base features only — target is plain sm_103)
// ---------------------------------------------------------------------------
__device__ __forceinline__ uint32_t smem_u32(const void* p) {
    uint32_t a;
    asm("{ .reg .u64 t; cvta.to.shared.u64 t, %1; cvt.u32.u64 %0, t; }" : "=r"(a) : "l"(p));
    return a;
}
__device__ __forceinline__ void cpasync16(uint32_t s, const void* g) {
    asm volatile("cp.async.cg.shared.global [%0], [%1], 16;\n" :: "r"(s), "l"(g));
}
#define CP_COMMIT() asm volatile("cp.async.commit_group;" ::: "memory")
#define CP_WAIT(n)  asm volatile("cp.async.wait_group %0;" :: "n"(n) : "memory")

#define LDSM4(r0, r1, r2, r3, addr) \
    asm volatile("ldmatrix.sync.aligned.m8n8.x4.shared.b16 {%0,%1,%2,%3}, [%4];" \
        : "=r"(r0), "=r"(r1), "=r"(r2), "=r"(r3) : "r"(addr))

#define MMA_BF16(d, a, b) \
    asm volatile("mma.sync.aligned.m16n8k16.row.col.f32.bf16.bf16.f32 " \
        "{%0,%1,%2,%3}, {%4,%5,%6,%7}, {%8,%9}, {%0,%1,%2,%3};" \
        : "+f"((d)[0]), "+f"((d)[1]), "+f"((d)[2]), "+f"((d)[3]) \
        : "r"((a)[0]), "r"((a)[1]), "r"((a)[2]), "r"((a)[3]), "r"((b)[0]), "r"((b)[1]))

// ---------------------------------------------------------------------------
// Generic split-bf16 HMMA GEMM:  D[i,j] = sum_k A[i,k]*B[j,k]
//   CTA tile 128(i) x 64(j), K-chunk 32, 2-stage cp.async.
//   4 warps (128 thr), warp grid 2(i) x 2(j), warp tile 64x32.
//   12 LDSM4 -> 48 MMAs per warp per k16 (ratio 4, was 3).
//   Targets 4 CTAs/SM (regs<=128, smem 48KB).
//   Stage layout (64B rows, XOR-4 swizzle on 16B chunks):
//     Ah @0 (8KB), Al @8192, Bh @16384 (4KB), Bl @20480; stride 24576.
//   mode 0: bf16 hi/lo out (+optional bias_i[i], bias_j[j]), out[j*ldo+i]
//   mode 1: fp32 out[j*ldo+i]
//   mode 2: fp32 out = D*inv[j] + shift[j] + xres  (BN + residual)
// ---------------------------------------------------------------------------
#define NTHR 128
#define STAGE_BYTES 24576
#define EPI_PITCH   132
#define SMEM_BYTES  49152    // 2 stages; epilogue staging (64*132*4=33792) reuses it

__device__ __forceinline__ uint32_t swz(int row, int ch) {
    return (uint32_t)(row * 64 + ((ch ^ (row & 3)) << 4));
}
__device__ __forceinline__ uint32_t ldsm_addr(uint32_t pbase, int rbase, int c0, int lane) {
    const int r = rbase + (lane & 15);
    const int c = c0 + (lane >> 4);
    return pbase + swz(r, c);
}

__device__ __forceinline__ void fill_stage(uint32_t sbase,
    const bf16* __restrict__ Ah, const bf16* __restrict__ Al,
    const bf16* __restrict__ Bh, const bf16* __restrict__ Bl,
    int i0, int j0, int koff, int K)
{
    const int t = threadIdx.x;
    // A planes: 128 rows x 4 chunks = 512 chunks, 4 per thread per plane
#pragma unroll
    for (int r = 0; r < 4; r++) {
        const int e = t + r * NTHR;
        const int row = e >> 2, ch = e & 3;
        const uint32_t so = swz(row, ch);
        const size_t ka = (size_t)(i0 + row) * K + koff + ch * 8;
        cpasync16(sbase + so,        Ah + ka);
        cpasync16(sbase + 8192 + so, Al + ka);
    }
    // B planes: 64 rows x 4 chunks = 256 chunks, 2 per thread per plane
#pragma unroll
    for (int r = 0; r < 2; r++) {
        const int e = t + r * NTHR;
        const int row = e >> 2, ch = e & 3;
        const uint32_t so = swz(row, ch);
        const size_t kb = (size_t)(j0 + row) * K + koff + ch * 8;
        cpasync16(sbase + 16384 + so, Bh + kb);
        cpasync16(sbase + 20480 + so, Bl + kb);
    }
}

__global__ __launch_bounds__(NTHR, 4)
void gemm_kernel(const bf16* __restrict__ Ahi, const bf16* __restrict__ Alo,
                 const bf16* __restrict__ Bhi, const bf16* __restrict__ Blo,
                 long long sA, long long sB, int K,
                 bf16* __restrict__ Ohi, bf16* __restrict__ Olo, float* __restrict__ O32,
                 long long sO, int ldo,
                 const float* __restrict__ bias_i, const float* __restrict__ bias_j,
                 int mode,
                 const float* __restrict__ gamma, const float* __restrict__ beta,
                 const float* __restrict__ mean, const float* __restrict__ var,
                 const float* __restrict__ wbias, const float* __restrict__ xres)
{
    extern __shared__ char dsm[];
    const int t = threadIdx.x, lane = t & 31, wid = t >> 5;
    const int wm = wid >> 1, wn = wid & 1;       // 2 x 2 warp grid, 64x32 tiles
    const int b = blockIdx.z;
    const int i0 = blockIdx.y * 128, j0 = blockIdx.x * 64;

    const bf16* Ah = Ahi + (size_t)b * sA;
    const bf16* Al = Alo + (size_t)b * sA;
    const bf16* Bh = Bhi + (size_t)b * sB;
    const bf16* Bl = Blo + (size_t)b * sB;

    const uint32_t sb = smem_u32(dsm);

    float acc[4][4][4] = {};

    const int nk = K >> 5;   // 32-wide K chunks

    fill_stage(sb, Ah, Al, Bh, Bl, i0, j0, 0, K);
    CP_COMMIT();

    for (int k = 0; k < nk; k++) {
        if (k + 1 < nk) {
            fill_stage(sb + ((k + 1) & 1) * STAGE_BYTES, Ah, Al, Bh, Bl, i0, j0, (k + 1) << 5, K);
            CP_COMMIT();
            CP_WAIT(1);
        } else {
            CP_WAIT(0);
        }
        __syncthreads();

        const uint32_t base = sb + (k & 1) * STAGE_BYTES;
#pragma unroll
        for (int ks = 0; ks < 2; ks++) {
            const int c0 = ks * 2;
            // B fragments first (held across mi loop)
            uint32_t bh[4][2], bl[4][2];
#pragma unroll
            for (int nip = 0; nip < 2; nip++) {
                const int rb = wn * 32 + nip * 16;
                uint32_t r0, r1, r2, r3;
                LDSM4(r0, r1, r2, r3, ldsm_addr(base + 16384, rb, c0, lane));
                bh[nip * 2][0] = r0; bh[nip * 2 + 1][0] = r1;
                bh[nip * 2][1] = r2; bh[nip * 2 + 1][1] = r3;
                LDSM4(r0, r1, r2, r3, ldsm_addr(base + 20480, rb, c0, lane));
                bl[nip * 2][0] = r0; bl[nip * 2 + 1][0] = r1;
                bl[nip * 2][1] = r2; bl[nip * 2 + 1][1] = r3;
            }
            // Stream A per 16-row tile: 2 LDSM4 -> 12 MMAs
#pragma unroll
            for (int mi = 0; mi < 4; mi++) {
                const int rb = wm * 64 + mi * 16;
                uint32_t ah[4], al[4];
                LDSM4(ah[0], ah[1], ah[2], ah[3], ldsm_addr(base,        rb, c0, lane));
                LDSM4(al[0], al[1], al[2], al[3], ldsm_addr(base + 8192, rb, c0, lane));
#pragma unroll
                for (int ni = 0; ni < 4; ni++) {
                    MMA_BF16(acc[mi][ni], ah, bh[ni]);
                    MMA_BF16(acc[mi][ni], ah, bl[ni]);
                    MMA_BF16(acc[mi][ni], al, bh[ni]);
                }
            }
        }
        __syncthreads();
    }

    // ---- epilogue: stage fp32 tile (128 x 64) through smem, coalesced out ----
    float* sf = (float*)dsm;
    {
        const int r0 = lane >> 2;
        const int cpair = (lane & 3) << 1;
#pragma unroll
        for (int mi = 0; mi < 4; mi++)
#pragma unroll
            for (int ni = 0; ni < 4; ni++) {
                const int il = wm * 64 + mi * 16 + r0;
                const int jl = wn * 32 + ni * 8 + cpair;
                sf[jl * EPI_PITCH + il]           = acc[mi][ni][0];
                sf[(jl + 1) * EPI_PITCH + il]     = acc[mi][ni][1];
                sf[jl * EPI_PITCH + il + 8]       = acc[mi][ni][2];
                sf[(jl + 1) * EPI_PITCH + il + 8] = acc[mi][ni][3];
            }
    }
    __syncthreads();

#pragma unroll 4
    for (int rep = 0; rep < 64; rep++) {
        const int idx = rep * NTHR + t;
        const int jl = idx >> 7, il = idx & 127;
        float v = sf[jl * EPI_PITCH + il];
        const int i = i0 + il;
        const int jg = j0 + jl;
        if (mode == 0) {
            if (bias_i) v += bias_i[i];
            if (bias_j) v += bias_j[jg];
            const bf16 h = __float2bfloat16(v);
            const float lo = v - __bfloat162float(h);
            const size_t a = (size_t)b * sO + (size_t)jg * ldo + i;
            Ohi[a] = h;
            Olo[a] = __float2bfloat16(lo);
        } else if (mode == 1) {
            O32[(size_t)b * sO + (size_t)jg * ldo + i] = v;
        } else {
            const float iv = gamma[jg] * rsqrtf(var[jg] + BN_EPS);
            const float sh = beta[jg] + (wbias[jg] - mean[jg]) * iv;
            const size_t a = (size_t)b * sO + (size_t)jg * ldo + i;
            O32[a] = v * iv + sh + xres[a];
        }
    }
}

// ---------------------------------------------------------------------------
// All 4 weight tensors split in one launch
// ---------------------------------------------------------------------------
#define W3_ELEMS (CI_DIM * C_DIM)
__global__ void conv_split4(const float* __restrict__ tw, const float* __restrict__ pw,
                            const float* __restrict__ gw, const float* __restrict__ ww)
{
    const int idx = blockIdx.x * 256 + threadIdx.x;
    const int sel = idx / W3_ELEMS;
    const int off = idx - sel * W3_ELEMS;
    const float* in = (sel == 0) ? tw : (sel == 1) ? pw : (sel == 2) ? gw : ww;
    bf16* hi = (sel == 0) ? g_tw_hi : (sel == 1) ? g_pw_hi : (sel == 2) ? g_gw_hi : g_ww_hi;
    bf16* lo = (sel == 0) ? g_tw_lo : (sel == 1) ? g_pw_lo : (sel == 2) ? g_gw_lo : g_ww_lo;
    const float v = in[off];
    const bf16 h = __float2bfloat16(v);
    hi[off] = h;
    lo[off] = __float2bfloat16(v - __bfloat162float(h));
}

// ---------------------------------------------------------------------------
// x [B,C,N] fp32 -> xT [B,N,C] bf16 hi/lo  (32x32 smem transpose)
// ---------------------------------------------------------------------------
__global__ __launch_bounds__(256)
void transpose_split(const float* __restrict__ x)
{
    __shared__ float tb[32][33];
    const int b = blockIdx.z;
    const int c0 = blockIdx.y * 32;
    const int n0 = blockIdx.x * 32;
    const int tx = threadIdx.x & 31, ty = threadIdx.x >> 5;
#pragma unroll
    for (int it = 0; it < 4; it++)
        tb[ty + it * 8][tx] = x[((size_t)b * C_DIM + c0 + ty + it * 8) * N_DIM + n0 + tx];
    __syncthreads();
#pragma unroll
    for (int it = 0; it < 4; it++) {
        const float v = tb[tx][ty + it * 8];
        const size_t a = ((size_t)b * N_DIM + n0 + ty + it * 8) * C_DIM + c0 + tx;
        const bf16 h = __float2bfloat16(v);
        g_xT_hi[a] = h;
        g_xT_lo[a] = __float2bfloat16(v - __bfloat162float(h));
    }
}

// ---------------------------------------------------------------------------
// Row softmax: S fp32 [row][2048] -> P hi/lo bf16
// ---------------------------------------------------------------------------
__global__ __launch_bounds__(256)
void softmax_split()
{
    const size_t row = (size_t)blockIdx.x * N_DIM;
    const float* __restrict__ s = g_S + row;
    __shared__ float buf[N_DIM];
    __shared__ float red[8];
    const int tid = threadIdx.x, lane = tid & 31, warp = tid >> 5;

    float lmax = -INFINITY;
#pragma unroll
    for (int it = 0; it < N_DIM / 256; it++) {
        float v = s[tid + it * 256];
        buf[tid + it * 256] = v;
        lmax = fmaxf(lmax, v);
    }
#pragma unroll
    for (int o = 16; o; o >>= 1) lmax = fmaxf(lmax, __shfl_xor_sync(0xffffffffu, lmax, o));
    if (lane == 0) red[warp] = lmax;
    __syncthreads();
    float m = red[0];
#pragma unroll
    for (int w = 1; w < 8; w++) m = fmaxf(m, red[w]);
    __syncthreads();

    float lsum = 0.f;
#pragma unroll
    for (int it = 0; it < N_DIM / 256; it++) {
        float e = __expf(buf[tid + it * 256] - m);
        buf[tid + it * 256] = e;
        lsum += e;
    }
#pragma unroll
    for (int o = 16; o; o >>= 1) lsum += __shfl_xor_sync(0xffffffffu, lsum, o);
    if (lane == 0) red[warp] = lsum;
    __syncthreads();
    float tot = red[0];
#pragma unroll
    for (int w = 1; w < 8; w++) tot += red[w];
    const float inv = 1.f / tot;

#pragma unroll
    for (int it = 0; it < N_DIM / 256; it++) {
        const int idx = tid + it * 256;
        const float p = buf[idx] * inv;
        const bf16 h = __float2bfloat16(p);
        g_P_hi[row + idx] = h;
        g_P_lo[row + idx] = __float2bfloat16(p - __bfloat162float(h));
    }
}

// ---------------------------------------------------------------------------
// Launch
// ---------------------------------------------------------------------------
extern "C" void kernel_launch(void* const* d_in, const int* in_sizes, int n_in,
                              void* d_out, int out_size)
{
    const float* x        = (const float*)d_in[0];
    const float* theta_w  = (const float*)d_in[1];
    const float* theta_b  = (const float*)d_in[2];
    const float* phi_w    = (const float*)d_in[3];
    const float* phi_b    = (const float*)d_in[4];
    const float* g_w      = (const float*)d_in[5];
    const float* g_b      = (const float*)d_in[6];
    const float* w_w      = (const float*)d_in[7];
    const float* w_b      = (const float*)d_in[8];
    const float* bn_gamma = (const float*)d_in[9];
    const float* bn_beta  = (const float*)d_in[10];
    const float* bn_mean  = (const float*)d_in[11];
    const float* bn_var   = (const float*)d_in[12];
    float* out = (float*)d_out;

    cudaFuncSetAttribute(gemm_kernel, cudaFuncAttributeMaxDynamicSharedMemorySize, SMEM_BYTES);

    bf16 *xt_hi, *xt_lo, *tw_hi, *tw_lo, *pw_hi, *pw_lo, *gw_hi, *gw_lo, *ww_hi, *ww_lo;
    bf16 *th_hi, *th_lo, *ph_hi, *ph_lo, *gv_hi, *gv_lo, *P_hi, *P_lo, *y_hi, *y_lo;
    float* Sp;
    cudaGetSymbolAddress((void**)&xt_hi, g_xT_hi); cudaGetSymbolAddress((void**)&xt_lo, g_xT_lo);
    cudaGetSymbolAddress((void**)&tw_hi, g_tw_hi); cudaGetSymbolAddress((void**)&tw_lo, g_tw_lo);
    cudaGetSymbolAddress((void**)&pw_hi, g_pw_hi); cudaGetSymbolAddress((void**)&pw_lo, g_pw_lo);
    cudaGetSymbolAddress((void**)&gw_hi, g_gw_hi); cudaGetSymbolAddress((void**)&gw_lo, g_gw_lo);
    cudaGetSymbolAddress((void**)&ww_hi, g_ww_hi); cudaGetSymbolAddress((void**)&ww_lo, g_ww_lo);
    cudaGetSymbolAddress((void**)&th_hi, g_th_hi); cudaGetSymbolAddress((void**)&th_lo, g_th_lo);
    cudaGetSymbolAddress((void**)&ph_hi, g_ph_hi); cudaGetSymbolAddress((void**)&ph_lo, g_ph_lo);
    cudaGetSymbolAddress((void**)&gv_hi, g_gv_hi); cudaGetSymbolAddress((void**)&gv_lo, g_gv_lo);
    cudaGetSymbolAddress((void**)&P_hi,  g_P_hi);  cudaGetSymbolAddress((void**)&P_lo,  g_P_lo);
    cudaGetSymbolAddress((void**)&y_hi,  g_y_hi);  cudaGetSymbolAddress((void**)&y_lo,  g_y_lo);
    cudaGetSymbolAddress((void**)&Sp,    g_S);

    // 0) weight splits (one launch) + x transpose/split
    conv_split4<<<4 * W3_ELEMS / 256, 256>>>(theta_w, phi_w, g_w, w_w);
    transpose_split<<<dim3(N_DIM / 32, C_DIM / 32, B_DIM), 256>>>(x);

    const long long sNC  = (long long)N_DIM * C_DIM;
    const long long sNCI = (long long)N_DIM * CI_DIM;
    const long long sCIN = (long long)CI_DIM * N_DIM;
    const long long sNN  = (long long)N_DIM * N_DIM;
    const long long sCN  = (long long)C_DIM * N_DIM;

    // 1) theta: D[o,n] = sum_c tw[o,c] * xT[n,c]  -> th [B,N,CI]
    gemm_kernel<<<dim3(N_DIM / 64, CI_DIM / 128, B_DIM), NTHR, SMEM_BYTES>>>(
        tw_hi, tw_lo, xt_hi, xt_lo, 0, sNC, C_DIM,
        th_hi, th_lo, nullptr, sNCI, CI_DIM, theta_b, nullptr, 0,
        nullptr, nullptr, nullptr, nullptr, nullptr, nullptr);
    // 2) phi
    gemm_kernel<<<dim3(N_DIM / 64, CI_DIM / 128, B_DIM), NTHR, SMEM_BYTES>>>(
        pw_hi, pw_lo, xt_hi, xt_lo, 0, sNC, C_DIM,
        ph_hi, ph_lo, nullptr, sNCI, CI_DIM, phi_b, nullptr, 0,
        nullptr, nullptr, nullptr, nullptr, nullptr, nullptr);
    // 3) g: D[n,ci] = sum_c xT[n,c] * gw[ci,c]  -> gv [B,CI,N]
    gemm_kernel<<<dim3(CI_DIM / 64, N_DIM / 128, B_DIM), NTHR, SMEM_BYTES>>>(
        xt_hi, xt_lo, gw_hi, gw_lo, sNC, 0, C_DIM,
        gv_hi, gv_lo, nullptr, sCIN, N_DIM, nullptr, g_b, 0,
        nullptr, nullptr, nullptr, nullptr, nullptr, nullptr);
    // 4) S: D[m,n] = sum_ci phi[m,ci] * theta[n,ci]  -> S fp32 [B,N,N]
    gemm_kernel<<<dim3(N_DIM / 64, N_DIM / 128, B_DIM), NTHR, SMEM_BYTES>>>(
        ph_hi, ph_lo, th_hi, th_lo, sNCI, sNCI, CI_DIM,
        nullptr, nullptr, Sp, sNN, N_DIM, nullptr, nullptr, 1,
        nullptr, nullptr, nullptr, nullptr, nullptr, nullptr);
    // 5) softmax rows -> P hi/lo
    softmax_split<<<B_DIM * N_DIM, 256>>>();
    // 6) y: D[ci,n] = sum_m gv[ci,m] * P[n,m]  -> y [B,N,CI]
    gemm_kernel<<<dim3(N_DIM / 64, CI_DIM / 128, B_DIM), NTHR, SMEM_BYTES>>>(
        gv_hi, gv_lo, P_hi, P_lo, sCIN, sNN, N_DIM,
        y_hi, y_lo, nullptr, sNCI, CI_DIM, nullptr, nullptr, 0,
        nullptr, nullptr, nullptr, nullptr, nullptr, nullptr);
    // 7) out: D[n,c] = sum_ci y[n,ci] * ww[c,ci], BN + residual
    gemm_kernel<<<dim3(C_DIM / 64, N_DIM / 128, B_DIM), NTHR, SMEM_BYTES>>>(
        y_hi, y_lo, ww_hi, ww_lo, sNCI, 0, CI_DIM,
        nullptr, nullptr, out, sCN, N_DIM, nullptr, nullptr, 2,
        bn_gamma, bn_beta, bn_mean, bn_var, w_b, x);
}